// round 13
// baseline (speedup 1.0000x reference)
#include <cuda_runtime.h>
#include <cuda_fp16.h>
#include <math.h>

#define BS 512
#define NN 256
#define MAXITER 200
#define OMEGA 1.5f

// smem float offsets
#define SM_EH    0                        // 256 half = 128 floats (scaled e-hat)
#define SM_WTOT  128                      // [2] norm accumulators (atomic)
#define SM_WRED  132                      // [8] setup partials
#define SM_WRED2 140                      // [8] setup partials
#define SM_MAT   160                      // 16 uint4-chunks x 256 rows = 16384 floats
#define SM_SCR   (SM_MAT + 16 * NN * 4)   // 8 * 1056 floats (fp32 inverse scratch)
#define SMEM_FLOATS (SM_SCR + 8 * 1056)   // 24992 floats = 99968 B (x2 CTAs/SM)

__device__ __forceinline__ __half2 u2h(unsigned int u) { return *(__half2*)&u; }
__device__ __forceinline__ unsigned int h2u(__half2 h) { return *(unsigned int*)&h; }

// warp-wide sum (setup only; sm_103 has no f32 redux)
__device__ __forceinline__ float warp_sum(float v) {
#pragma unroll
    for (int o = 16; o; o >>= 1) v += __shfl_xor_sync(0xffffffffu, v, o);
    return v;
}

// consume 32-col block Q (chunks 4Q..4Q+3): acc -= sp * C[:,Q]·ehat[Q]
// two 8-deep half2 chains, one upconvert each
template<int Q>
__device__ __forceinline__ void consume32(float& acc, float sp,
        const uint4* cregs, const uint4* __restrict__ sH4,
        const uint4* __restrict__ eh4, int tid)
{
    const int c0 = 4*Q, c1 = 4*Q+1, c2 = 4*Q+2, c3 = 4*Q+3;
    const uint4 ca = (c0 < 16) ? cregs[c0] : sH4[(c0-16)*NN + tid];
    const uint4 cb = (c1 < 16) ? cregs[c1] : sH4[(c1-16)*NN + tid];
    const uint4 cc = (c2 < 16) ? cregs[c2] : sH4[(c2-16)*NN + tid];
    const uint4 cd = (c3 < 16) ? cregs[c3] : sH4[(c3-16)*NN + tid];
    const uint4 ea = eh4[c0], eb = eh4[c1], ec = eh4[c2], ed = eh4[c3];
    __half2 h0 = __hmul2(u2h(ca.x), u2h(ea.x));
    h0 = __hfma2(u2h(ca.y), u2h(ea.y), h0);
    h0 = __hfma2(u2h(ca.z), u2h(ea.z), h0);
    h0 = __hfma2(u2h(ca.w), u2h(ea.w), h0);
    h0 = __hfma2(u2h(cb.x), u2h(eb.x), h0);
    h0 = __hfma2(u2h(cb.y), u2h(eb.y), h0);
    h0 = __hfma2(u2h(cb.z), u2h(eb.z), h0);
    h0 = __hfma2(u2h(cb.w), u2h(eb.w), h0);
    __half2 h1 = __hmul2(u2h(cc.x), u2h(ec.x));
    h1 = __hfma2(u2h(cc.y), u2h(ec.y), h1);
    h1 = __hfma2(u2h(cc.z), u2h(ec.z), h1);
    h1 = __hfma2(u2h(cc.w), u2h(ec.w), h1);
    h1 = __hfma2(u2h(cd.x), u2h(ed.x), h1);
    h1 = __hfma2(u2h(cd.y), u2h(ed.y), h1);
    h1 = __hfma2(u2h(cd.z), u2h(ed.z), h1);
    h1 = __hfma2(u2h(cd.w), u2h(ed.w), h1);
    const float2 f0 = __half22float2(h0);
    const float2 f1 = __half22float2(h1);
    acc = fmaf(-sp, (f0.x + f0.y) + (f1.x + f1.y), acc);
}

// warp-local 32x32 unit-lower solve: e_new = Minv * acc; publish scaled; reinit acc
__device__ __forceinline__ void solve32(float& acc, float& normv,
        const float* __restrict__ Mrow, __half* __restrict__ eh,
        float inv_sp, int tid)
{
    const float r = acc;
    float e0 = 0.f, e1 = 0.f, e2 = 0.f, e3 = 0.f;
#pragma unroll
    for (int k = 0; k < 32; k += 4) {
        e0 = fmaf(Mrow[k+0], __shfl_sync(0xffffffffu, r, k+0), e0);
        e1 = fmaf(Mrow[k+1], __shfl_sync(0xffffffffu, r, k+1), e1);
        e2 = fmaf(Mrow[k+2], __shfl_sync(0xffffffffu, r, k+2), e2);
        e3 = fmaf(Mrow[k+3], __shfl_sync(0xffffffffu, r, k+3), e3);
    }
    const float en = (e0 + e1) + (e2 + e3);
    eh[tid] = __float2half(en * inv_sp);   // publish e-hat
    acc = (1.0f - OMEGA) * en;             // start next iteration's accumulator
    normv = en * en;
}

// fire-and-forget norm contribution (no return value -> off the warp's path)
__device__ __forceinline__ void norm_pub(float normv, float* __restrict__ wtot, int bank)
{
    atomicAdd(&wtot[bank], normv);
}

__global__ void __launch_bounds__(NN, 2) sor_fused(
    const float* __restrict__ A, const float* __restrict__ xs,
    const float* __restrict__ theta, const float* __restrict__ rtol,
    float* __restrict__ out)
{
    extern __shared__ float sm[];
    __half*      eh   = (__half*)(sm + SM_EH);
    const uint4* eh4  = (const uint4*)(sm + SM_EH);
    float*       wtot = sm + SM_WTOT;
    float*       wred = sm + SM_WRED;
    float*       wred2= sm + SM_WRED2;
    uint4*       sH4  = (uint4*)(sm + SM_MAT);
    float*       scr  = sm + SM_SCR;

    const int b = blockIdx.x, tid = threadIdx.x;
    const int wid = tid >> 5, lane = tid & 31;
    const size_t obase = (size_t)b * (MAXITER + 1);

    // -------- load row tid, scale by omega/a_ii, stage fp32 diag block, zero own
    //          lower (j<=tid), convert to half2, split regs/smem ----------------
    const float*  Ar  = A + ((size_t)b * NN + tid) * NN;
    const float4* Ar4 = (const float4*)Ar;
    const float sc = OMEGA / Ar[tid];
    float* myscr = scr + wid * 1056;
    uint4 cregs[16];
#pragma unroll
    for (int ch = 0; ch < 32; ++ch) {        // chunk = 8 cols
        float4 u = Ar4[2*ch+0], v = Ar4[2*ch+1];
        u.x *= sc; u.y *= sc; u.z *= sc; u.w *= sc;
        v.x *= sc; v.y *= sc; v.z *= sc; v.w *= sc;
        if ((ch >> 2) == wid) {              // chunk inside own 32-col block
            float cols[8] = {u.x,u.y,u.z,u.w,v.x,v.y,v.z,v.w};
            const int base = (ch & 3) * 8;
#pragma unroll
            for (int k = 0; k < 8; ++k) myscr[lane*33 + base + k] = cols[k];
#pragma unroll
            for (int k = 0; k < 8; ++k) if (8*ch + k <= tid) cols[k] = 0.f;
            u.x=cols[0]; u.y=cols[1]; u.z=cols[2]; u.w=cols[3];
            v.x=cols[4]; v.y=cols[5]; v.z=cols[6]; v.w=cols[7];
        }
        uint4 h;
        h.x = h2u(__floats2half2_rn(u.x, u.y));
        h.y = h2u(__floats2half2_rn(u.z, u.w));
        h.z = h2u(__floats2half2_rn(v.x, v.y));
        h.w = h2u(__floats2half2_rn(v.z, v.w));
        if (ch < 16) cregs[ch] = h;
        else         sH4[(ch - 16) * NN + tid] = h;
    }

    // -------- e0 = xs - theta; warp-partial norms; zero atomic banks ------------
    const float xv = xs[b * NN + tid];
    const float e0v = xv - theta[b * NN + tid];
    {
        const float s1 = warp_sum(e0v * e0v);
        const float s2 = warp_sum(xv * xv);
        if (lane == 0) { wred[wid] = s1; wred2[wid] = s2; }
        if (tid == 0) { wtot[0] = 0.f; wtot[1] = 0.f; }
    }

    // -------- per-warp 32x32 unit-lower inverse in scr --------------------------
    __syncwarp();
    {
        float mcol[32];
#pragma unroll
        for (int r = 0; r < 32; ++r) mcol[r] = (r == lane) ? 1.f : 0.f;
#pragma unroll
        for (int r = 1; r < 32; ++r) {
            float s = 0.f;
#pragma unroll
            for (int j = 0; j < r; ++j) s = fmaf(myscr[r * 33 + j], mcol[j], s);
            mcol[r] -= s;
        }
        __syncwarp();
#pragma unroll
        for (int r = 0; r < 32; ++r) myscr[r * 33 + lane] = mcol[r];
    }
    __syncwarp();
    float Mrow[32];
#pragma unroll
    for (int c = 0; c < 32; ++c) Mrow[c] = myscr[lane * 33 + c];

    __syncthreads();   // wred/wred2/wtot + sH4 visible

    // -------- err0 / xtol2 (identical in every thread); publish e-hat -----------
    float sp_cur, xtol2, inv_sp;
    {
        float a1 = 0.f, a2 = 0.f;
#pragma unroll
        for (int w = 0; w < 8; ++w) { a1 += wred[w]; a2 += wred2[w]; }
        const float rt = rtol[b];
        sp_cur = sqrtf(a1);                 // err0
        inv_sp = rsqrtf(a1);
        xtol2  = a2 * rt * rt;
        if (tid == 0) out[obase] = sp_cur;
        if (a1 <= xtol2) {                  // degenerate: converged at t=0
            for (int z = 1 + tid; z <= MAXITER; z += NN) out[obase + z] = 0.f;
            return;
        }
    }
    eh[tid] = __float2half(e0v * inv_sp);
    __syncthreads();   // e-hat visible

    // -------- prologue: warp p consumes blocks p..7 of e0 (scale err0) ----------
    float acc = (1.0f - OMEGA) * e0v;
    if (wid == 0) consume32<0>(acc, sp_cur, cregs, sH4, eh4, tid);
    if (wid <= 1) consume32<1>(acc, sp_cur, cregs, sH4, eh4, tid);
    if (wid <= 2) consume32<2>(acc, sp_cur, cregs, sH4, eh4, tid);
    if (wid <= 3) consume32<3>(acc, sp_cur, cregs, sH4, eh4, tid);
    if (wid <= 4) consume32<4>(acc, sp_cur, cregs, sH4, eh4, tid);
    if (wid <= 5) consume32<5>(acc, sp_cur, cregs, sH4, eh4, tid);
    if (wid <= 6) consume32<6>(acc, sp_cur, cregs, sH4, eh4, tid);
    consume32<7>(acc, sp_cur, cregs, sH4, eh4, tid);

    // -------- pipelined mainloop: 8 warp-local stages ---------------------------
    float normv = 0.f;
    int t = 1;
    for (; t <= MAXITER; ++t) {
        // ===== stage 0 =====
        __syncthreads();                    // block 7 of iter t-1 + norm atomics drained
        const float sp_old = sp_cur;
        if (t > 1) {
            const float s = wtot[(t - 1) & 1];   // broadcast LDS
            sp_cur = sqrtf(s);
            inv_sp = rsqrtf(s);
            if (tid == 0) out[obase + (t - 1)] = sp_cur;
            if (s <= xtol2) break;
        }
        if (t > 1) consume32<7>(acc, sp_old, cregs, sH4, eh4, tid);
        if (wid == 0) solve32(acc, normv, Mrow, eh, inv_sp, tid);

#define STAGE(S)                                                               \
        if (wid == S-1) { asm volatile("bar.arrive %0, %1;"                    \
                              :: "r"(S), "r"(NN) : "memory"); }                \
        else            { asm volatile("bar.sync %0, %1;"                      \
                              :: "r"(S), "r"(NN) : "memory"); }                \
        if (S == 4 && tid == 0) wtot[(t + 1) & 1] = 0.f;                       \
        consume32<S-1>(acc, sp_cur, cregs, sH4, eh4, tid);                     \
        if (wid == S-1) norm_pub(normv, wtot, t & 1);                          \
        if (wid == S)   solve32(acc, normv, Mrow, eh, inv_sp, tid);

        STAGE(1) STAGE(2) STAGE(3) STAGE(4) STAGE(5) STAGE(6) STAGE(7)
#undef STAGE
        if (wid == 7) norm_pub(normv, wtot, t & 1);
    }

    // -------- epilogue -----------------------------------------------------------
    int zf;
    if (t > MAXITER) {                      // natural exit: err_MAXITER unwritten
        __syncthreads();
        const float s = wtot[MAXITER & 1];
        if (tid == 0) out[obase + MAXITER] = sqrtf(s);
        zf = MAXITER + 1;
    } else {
        zf = t;                             // broke at pass t: zero t..MAXITER
    }
    for (int z = zf + tid; z <= MAXITER; z += NN)
        out[obase + z] = 0.f;
}

// ---------------------------------------------------------------------------
extern "C" void kernel_launch(void* const* d_in, const int* in_sizes, int n_in,
                              void* d_out, int out_size) {
    const float* A     = (const float*)d_in[0];
    // d_in[1] = b — not needed (error-vector formulation)
    const float* xs    = (const float*)d_in[2];
    const float* theta = (const float*)d_in[3];
    const float* rtol  = (const float*)d_in[4];
    float* out = (float*)d_out;

    static int smem_set = 0;
    if (!smem_set) {
        cudaFuncSetAttribute(sor_fused, cudaFuncAttributeMaxDynamicSharedMemorySize,
                             SMEM_FLOATS * (int)sizeof(float));
        smem_set = 1;
    }
    sor_fused<<<BS, NN, SMEM_FLOATS * sizeof(float)>>>(A, xs, theta, rtol, out);
}

// round 14
// speedup vs baseline: 3.4778x; 3.4778x over previous
#include <cuda_runtime.h>
#include <cuda_fp16.h>
#include <math.h>

#define BS 512
#define NN 256
#define MAXITER 200
#define OMEGA 1.5f

// smem float offsets
#define SM_EH    0                        // 256 half = 128 floats (scaled e-hat)
#define SM_WRED  128                      // [2][8]
#define SM_WRED2 144                      // [8]
#define SM_MAT   160                      // 16 uint4-chunks x 256 rows = 16384 floats
#define SM_SCR   (SM_MAT + 16 * NN * 4)   // 8 * 1056 floats (fp32 inverse scratch)
#define SMEM_FLOATS (SM_SCR + 8 * 1056)   // 24992 floats = 99968 B (x2 CTAs/SM)

__device__ __forceinline__ __half2 u2h(unsigned int u) { return *(__half2*)&u; }
__device__ __forceinline__ unsigned int h2u(__half2 h) { return *(unsigned int*)&h; }

// warp-wide sum (sm_103 has no f32 redux — butterfly shuffles)
__device__ __forceinline__ float warp_sum(float v) {
#pragma unroll
    for (int o = 16; o; o >>= 1) v += __shfl_xor_sync(0xffffffffu, v, o);
    return v;
}

// consume 32-col block Q (chunks 4Q..4Q+3): acc -= sp * C[:,Q]·ehat[Q]
// diet version: two 8-deep half2 FMA chains, one upconvert each
template<int Q>
__device__ __forceinline__ void consume32(float& acc, float sp,
        const uint4* cregs, const uint4* __restrict__ sH4,
        const uint4* __restrict__ eh4, int tid)
{
    const int c0 = 4*Q, c1 = 4*Q+1, c2 = 4*Q+2, c3 = 4*Q+3;
    const uint4 ca = (c0 < 16) ? cregs[c0] : sH4[(c0-16)*NN + tid];
    const uint4 cb = (c1 < 16) ? cregs[c1] : sH4[(c1-16)*NN + tid];
    const uint4 cc = (c2 < 16) ? cregs[c2] : sH4[(c2-16)*NN + tid];
    const uint4 cd = (c3 < 16) ? cregs[c3] : sH4[(c3-16)*NN + tid];
    const uint4 ea = eh4[c0], eb = eh4[c1], ec = eh4[c2], ed = eh4[c3];
    __half2 h0 = __hmul2(u2h(ca.x), u2h(ea.x));
    h0 = __hfma2(u2h(ca.y), u2h(ea.y), h0);
    h0 = __hfma2(u2h(ca.z), u2h(ea.z), h0);
    h0 = __hfma2(u2h(ca.w), u2h(ea.w), h0);
    h0 = __hfma2(u2h(cb.x), u2h(eb.x), h0);
    h0 = __hfma2(u2h(cb.y), u2h(eb.y), h0);
    h0 = __hfma2(u2h(cb.z), u2h(eb.z), h0);
    h0 = __hfma2(u2h(cb.w), u2h(eb.w), h0);
    __half2 h1 = __hmul2(u2h(cc.x), u2h(ec.x));
    h1 = __hfma2(u2h(cc.y), u2h(ec.y), h1);
    h1 = __hfma2(u2h(cc.z), u2h(ec.z), h1);
    h1 = __hfma2(u2h(cc.w), u2h(ec.w), h1);
    h1 = __hfma2(u2h(cd.x), u2h(ed.x), h1);
    h1 = __hfma2(u2h(cd.y), u2h(ed.y), h1);
    h1 = __hfma2(u2h(cd.z), u2h(ed.z), h1);
    h1 = __hfma2(u2h(cd.w), u2h(ed.w), h1);
    const float2 f0 = __half22float2(h0);
    const float2 f1 = __half22float2(h1);
    acc = fmaf(-sp, (f0.x + f0.y) + (f1.x + f1.y), acc);
}

// warp-local 32x32 unit-lower solve: e_new = Minv * acc; publish scaled; reinit acc
__device__ __forceinline__ void solve32(float& acc, float& normv,
        const float* __restrict__ Mrow, __half* __restrict__ eh,
        float inv_sp, int tid)
{
    const float r = acc;
    float e0 = 0.f, e1 = 0.f, e2 = 0.f, e3 = 0.f;
#pragma unroll
    for (int k = 0; k < 32; k += 4) {
        e0 = fmaf(Mrow[k+0], __shfl_sync(0xffffffffu, r, k+0), e0);
        e1 = fmaf(Mrow[k+1], __shfl_sync(0xffffffffu, r, k+1), e1);
        e2 = fmaf(Mrow[k+2], __shfl_sync(0xffffffffu, r, k+2), e2);
        e3 = fmaf(Mrow[k+3], __shfl_sync(0xffffffffu, r, k+3), e3);
    }
    const float en = (e0 + e1) + (e2 + e3);
    eh[tid] = __float2half(en * inv_sp);   // publish e-hat
    acc = (1.0f - OMEGA) * en;             // start next iteration's accumulator
    normv = en * en;
}

__device__ __forceinline__ void norm_pub(float normv, float* __restrict__ wred,
                                         int bank, int wid, int lane)
{
    const float v = warp_sum(normv);
    if (lane == 0) wred[bank * 8 + wid] = v;
}

__global__ void __launch_bounds__(NN, 2) sor_fused(
    const float* __restrict__ A, const float* __restrict__ xs,
    const float* __restrict__ theta, const float* __restrict__ rtol,
    float* __restrict__ out)
{
    extern __shared__ float sm[];
    __half*      eh   = (__half*)(sm + SM_EH);
    const uint4* eh4  = (const uint4*)(sm + SM_EH);
    float*       wred = sm + SM_WRED;
    float*       wred2= sm + SM_WRED2;
    uint4*       sH4  = (uint4*)(sm + SM_MAT);
    float*       scr  = sm + SM_SCR;

    const int b = blockIdx.x, tid = threadIdx.x;
    const int wid = tid >> 5, lane = tid & 31;
    const size_t obase = (size_t)b * (MAXITER + 1);

    // -------- load row tid, scale by omega/a_ii, stage fp32 diag block, zero own
    //          lower (j<=tid), convert to half2, split regs/smem ----------------
    const float*  Ar  = A + ((size_t)b * NN + tid) * NN;
    const float4* Ar4 = (const float4*)Ar;
    const float sc = OMEGA / Ar[tid];
    float* myscr = scr + wid * 1056;
    uint4 cregs[16];
#pragma unroll
    for (int ch = 0; ch < 32; ++ch) {        // chunk = 8 cols
        float4 u = Ar4[2*ch+0], v = Ar4[2*ch+1];
        u.x *= sc; u.y *= sc; u.z *= sc; u.w *= sc;
        v.x *= sc; v.y *= sc; v.z *= sc; v.w *= sc;
        if ((ch >> 2) == wid) {              // chunk inside own 32-col block
            float cols[8] = {u.x,u.y,u.z,u.w,v.x,v.y,v.z,v.w};
            const int base = (ch & 3) * 8;
#pragma unroll
            for (int k = 0; k < 8; ++k) myscr[lane*33 + base + k] = cols[k];
#pragma unroll
            for (int k = 0; k < 8; ++k) if (8*ch + k <= tid) cols[k] = 0.f;
            u.x=cols[0]; u.y=cols[1]; u.z=cols[2]; u.w=cols[3];
            v.x=cols[4]; v.y=cols[5]; v.z=cols[6]; v.w=cols[7];
        }
        uint4 h;
        h.x = h2u(__floats2half2_rn(u.x, u.y));
        h.y = h2u(__floats2half2_rn(u.z, u.w));
        h.z = h2u(__floats2half2_rn(v.x, v.y));
        h.w = h2u(__floats2half2_rn(v.z, v.w));
        if (ch < 16) cregs[ch] = h;
        else         sH4[(ch - 16) * NN + tid] = h;
    }

    // -------- e0 = xs - theta; warp-partial norms -------------------------------
    const float xv = xs[b * NN + tid];
    const float e0v = xv - theta[b * NN + tid];
    {
        const float s1 = warp_sum(e0v * e0v);
        const float s2 = warp_sum(xv * xv);
        if (lane == 0) { wred[wid] = s1; wred2[wid] = s2; }
    }

    // -------- per-warp 32x32 unit-lower inverse in scr --------------------------
    __syncwarp();
    {
        float mcol[32];
#pragma unroll
        for (int r = 0; r < 32; ++r) mcol[r] = (r == lane) ? 1.f : 0.f;
#pragma unroll
        for (int r = 1; r < 32; ++r) {
            float s = 0.f;
#pragma unroll
            for (int j = 0; j < r; ++j) s = fmaf(myscr[r * 33 + j], mcol[j], s);
            mcol[r] -= s;
        }
        __syncwarp();
#pragma unroll
        for (int r = 0; r < 32; ++r) myscr[r * 33 + lane] = mcol[r];
    }
    __syncwarp();
    float Mrow[32];
#pragma unroll
    for (int c = 0; c < 32; ++c) Mrow[c] = myscr[lane * 33 + c];

    __syncthreads();   // wred/wred2 + sH4 visible

    // -------- err0 / xtol2 (identical in every thread); publish e-hat -----------
    float sp_cur, xtol2, inv_sp;
    {
        float a1 = 0.f, a2 = 0.f;
#pragma unroll
        for (int w = 0; w < 8; ++w) { a1 += wred[w]; a2 += wred2[w]; }
        const float rt = rtol[b];
        sp_cur = sqrtf(a1);                 // err0
        inv_sp = rsqrtf(a1);
        xtol2  = a2 * rt * rt;
        if (tid == 0) out[obase] = sp_cur;
        if (a1 <= xtol2) {                  // degenerate: converged at t=0
            for (int z = 1 + tid; z <= MAXITER; z += NN) out[obase + z] = 0.f;
            return;
        }
    }
    eh[tid] = __float2half(e0v * inv_sp);
    __syncthreads();   // e-hat visible

    // -------- prologue: warp p consumes blocks p..7 of e0 (scale err0) ----------
    float acc = (1.0f - OMEGA) * e0v;
    if (wid == 0) consume32<0>(acc, sp_cur, cregs, sH4, eh4, tid);
    if (wid <= 1) consume32<1>(acc, sp_cur, cregs, sH4, eh4, tid);
    if (wid <= 2) consume32<2>(acc, sp_cur, cregs, sH4, eh4, tid);
    if (wid <= 3) consume32<3>(acc, sp_cur, cregs, sH4, eh4, tid);
    if (wid <= 4) consume32<4>(acc, sp_cur, cregs, sH4, eh4, tid);
    if (wid <= 5) consume32<5>(acc, sp_cur, cregs, sH4, eh4, tid);
    if (wid <= 6) consume32<6>(acc, sp_cur, cregs, sH4, eh4, tid);
    consume32<7>(acc, sp_cur, cregs, sH4, eh4, tid);

    // -------- pipelined mainloop: 8 warp-local stages ---------------------------
    float normv = 0.f;
    int t = 1;
    for (; t <= MAXITER; ++t) {
        // ===== stage 0 =====
        __syncthreads();                    // block 7 of iter t-1 + all norms ready
        const float sp_old = sp_cur;
        if (t > 1) {
            const int bk = ((t - 1) & 1) * 8;
            const float4 w0 = *(const float4*)&wred[bk];
            const float4 w1 = *(const float4*)&wred[bk + 4];
            const float s = ((w0.x + w0.y) + (w0.z + w0.w))
                          + ((w1.x + w1.y) + (w1.z + w1.w));
            sp_cur = sqrtf(s);
            inv_sp = rsqrtf(s);
            if (tid == 0) out[obase + (t - 1)] = sp_cur;
            if (s <= xtol2) break;
        }
        if (t > 1) consume32<7>(acc, sp_old, cregs, sH4, eh4, tid);
        if (wid == 0) solve32(acc, normv, Mrow, eh, inv_sp, tid);

#define STAGE(S)                                                               \
        if (wid == S-1) { asm volatile("bar.arrive %0, %1;"                    \
                              :: "r"(S), "r"(NN) : "memory"); }                \
        else            { asm volatile("bar.sync %0, %1;"                      \
                              :: "r"(S), "r"(NN) : "memory"); }                \
        consume32<S-1>(acc, sp_cur, cregs, sH4, eh4, tid);                     \
        if (wid == S-1) norm_pub(normv, wred, t & 1, wid, lane);               \
        if (wid == S)   solve32(acc, normv, Mrow, eh, inv_sp, tid);

        STAGE(1) STAGE(2) STAGE(3) STAGE(4) STAGE(5) STAGE(6) STAGE(7)
#undef STAGE
        if (wid == 7) norm_pub(normv, wred, t & 1, wid, lane);
    }

    // -------- epilogue -----------------------------------------------------------
    int zf;
    if (t > MAXITER) {                      // natural exit: err_MAXITER unwritten
        __syncthreads();
        const int bk = (MAXITER & 1) * 8;
        float s = 0.f;
#pragma unroll
        for (int w = 0; w < 8; ++w) s += wred[bk + w];
        if (tid == 0) out[obase + MAXITER] = sqrtf(s);
        zf = MAXITER + 1;
    } else {
        zf = t;                             // broke at pass t: zero t..MAXITER
    }
    for (int z = zf + tid; z <= MAXITER; z += NN)
        out[obase + z] = 0.f;
}

// ---------------------------------------------------------------------------
extern "C" void kernel_launch(void* const* d_in, const int* in_sizes, int n_in,
                              void* d_out, int out_size) {
    const float* A     = (const float*)d_in[0];
    // d_in[1] = b — not needed (error-vector formulation)
    const float* xs    = (const float*)d_in[2];
    const float* theta = (const float*)d_in[3];
    const float* rtol  = (const float*)d_in[4];
    float* out = (float*)d_out;

    static int smem_set = 0;
    if (!smem_set) {
        cudaFuncSetAttribute(sor_fused, cudaFuncAttributeMaxDynamicSharedMemorySize,
                             SMEM_FLOATS * (int)sizeof(float));
        smem_set = 1;
    }
    sor_fused<<<BS, NN, SMEM_FLOATS * sizeof(float)>>>(A, xs, theta, rtol, out);
}